// round 12
// baseline (speedup 1.0000x reference)
#include <cuda_runtime.h>
#include <cuda_fp16.h>
#include <cstdint>

typedef unsigned int u32;

// ---- SMEM layout (byte offsets) ----
#define O_H    0         // u32 h[128][136]  f16x2 pairs, fragment-permuted, stride 136
#define O_XA   69632     // u32 xa[128][24]  compacted active-col activations
#define O_YE   81920     // float yE[128][34]
#define O_YO   99328     // float yO[128][34]
#define O_LDP  116736    // float ldp[128][4]
#define SMEM_REQ 118784

#define LN4Q 10240       // uint4 per (layer,net) weight block
__device__ __align__(256) uint4 g_wb[16 * LN4Q + 1024];  // +16KB pad for prefetch overrun

// ---------------- helpers ----------------
__device__ __forceinline__ float tanhf_(float x) {
    float e = __expf(2.0f * x);
    return 1.0f - __fdividef(2.0f, e + 1.0f);
}
__device__ __forceinline__ u32 h2pack(float a, float b) {
    __half2 h = __floats2half2_rn(a, b);
    return *(u32*)&h;
}
// fragment-permuted pair position: pair index pi -> u32 index within row
__device__ __host__ __forceinline__ int posperm(int pi) {
    return ((pi >> 3) << 3) + 2 * (pi & 3) + ((pi >> 2) & 1);
}
__device__ __forceinline__ void mma16816(float* d, u32 a0, u32 a1, u32 a2, u32 a3,
                                         u32 b0, u32 b1) {
    asm volatile(
        "mma.sync.aligned.m16n8k16.row.col.f32.f16.f16.f32 "
        "{%0,%1,%2,%3}, {%4,%5,%6,%7}, {%8,%9}, {%0,%1,%2,%3};"
        : "+f"(d[0]), "+f"(d[1]), "+f"(d[2]), "+f"(d[3])
        : "r"(a0), "r"(a1), "r"(a2), "r"(a3), "r"(b0), "r"(b1));
}
#define BARS() asm volatile("bar.sync %0, %1;" :: "r"(strip + 1), "r"(128) : "memory")

// ---------------- prep: pack fp16 weights, two n-tiles per uint4 ----------------
// Per (layer,net) block of LN4Q uint4:
//  G1 @0     : 2ks x 16np x 32lane   (K=32 compacted to mask-active dims)
//  G2 @1024  : 16ks x 16np x 32lane  (identity folded: W2' = W2 + I)
//  G3 @9216  : 16ks x 2np x 32lane   (N=32 compacted to (1-m)=1 output dims)
// uint4 = { frag(nt=2np), frag(nt=2np+1) }, frag uint2 = {f16x2(w0,w1), f16x2(w8,w9)}.
__device__ __forceinline__ uint2 mkfrag(int g, int layer, int net, int ks, int nt, int lane,
    const float* sW1, const float* sW2, const float* sW3,
    const float* tW1, const float* tW2, const float* tW3)
{
    float w0, w1, w8, w9;
    int n = nt * 8 + (lane >> 2);
    if (g == 0) {
        int par = layer & 1;
        const float* wr = (net ? tW1 : sW1) + (size_t)layer * 16384
                        + n * 64 + (ks * 16 + (lane & 3) * 2) * 2 + par;
        w0 = wr[0]; w1 = wr[2]; w8 = wr[16]; w9 = wr[18];
    } else if (g == 1) {
        int k = ks * 16 + (lane & 3) * 2;
        const float* wr = (net ? tW2 : sW2) + (size_t)layer * 65536 + (size_t)n * 256 + k;
        w0 = wr[0] + (n == k     ? 1.f : 0.f);
        w1 = wr[1] + (n == k + 1 ? 1.f : 0.f);
        w8 = wr[8] + (n == k + 8 ? 1.f : 0.f);
        w9 = wr[9] + (n == k + 9 ? 1.f : 0.f);
    } else {
        int op = (layer & 1) ^ 1;
        const float* wr = (net ? tW3 : sW3) + (size_t)layer * 16384
                        + (2 * n + op) * 256 + ks * 16 + (lane & 3) * 2;
        w0 = wr[0]; w1 = wr[1]; w8 = wr[8]; w9 = wr[9];
    }
    return make_uint2(h2pack(w0, w1), h2pack(w8, w9));
}

__global__ void prep(const float* __restrict__ sW1, const float* __restrict__ sW2,
                     const float* __restrict__ sW3, const float* __restrict__ tW1,
                     const float* __restrict__ tW2, const float* __restrict__ tW3)
{
    int t = blockIdx.x * blockDim.x + threadIdx.x;
    if (t >= 16 * LN4Q) return;
    int ln = t / LN4Q, rem = t % LN4Q;
    int layer = ln >> 1, net = ln & 1;
    int g, ks, np, lane;
    if (rem < 1024)      { g = 0; ks = rem >> 9; np = (rem >> 5) & 15; lane = rem & 31; }
    else if (rem < 9216) { int q = rem - 1024; g = 1; ks = q >> 9; np = (q >> 5) & 15; lane = q & 31; }
    else                 { int q = rem - 9216; g = 2; ks = q >> 6; np = (q >> 5) & 1;  lane = q & 31; }
    uint2 f0 = mkfrag(g, layer, net, ks, 2 * np,     lane, sW1, sW2, sW3, tW1, tW2, tW3);
    uint2 f1 = mkfrag(g, layer, net, ks, 2 * np + 1, lane, sW1, sW2, sW3, tW1, tW2, tW3);
    g_wb[t] = make_uint4(f0.x, f0.y, f1.x, f1.y);
}

// ---------------- GEMM, M=16/warp, 8 n-tiles, B streamed JIT with uint4 packing ----------------
template<int KS, int AST>
__device__ __forceinline__ void gemm8(float (&acc)[8][4],
                                      const uint4* __restrict__ Bw,
                                      const u32* __restrict__ Arow, int lane)
{
#pragma unroll
    for (int j = 0; j < 8; j++)
#pragma unroll
        for (int i = 0; i < 4; i++) acc[j][i] = 0.f;

    uint4 bf[4];
#pragma unroll
    for (int j = 0; j < 4; j++) bf[j] = Bw[j * 32];
    const u32* ap = Arow + (lane >> 2) * AST + 2 * (lane & 3);

#pragma unroll 1
    for (int ks = 0; ks < KS; ks++) {
        uint2 v0 = *(const uint2*)(ap + ks * 8);
        uint2 v1 = *(const uint2*)(ap + 8 * AST + ks * 8);
        u32 a0 = v0.x, a2 = v0.y, a1 = v1.x, a3 = v1.y;
        const uint4* bq = Bw + (ks + 1) * 512;
#pragma unroll
        for (int j = 0; j < 4; j++) {
            uint4 b = bf[j]; bf[j] = bq[j * 32];      // refill from ks+1 (pad covers tail)
            mma16816(acc[2 * j],     a0, a1, a2, a3, b.x, b.y);
            mma16816(acc[2 * j + 1], a0, a1, a2, a3, b.z, b.w);
        }
    }
}

// G3: 1 n-tile/warp (N=32 compacted), K=256, M=16
__device__ __forceinline__ void gemm1(float (&a4)[4],
                                      const uint2* __restrict__ Bw,
                                      const u32* __restrict__ Arow, int lane)
{
#pragma unroll
    for (int i = 0; i < 4; i++) a4[i] = 0.f;
    uint2 bf = Bw[0];
    const u32* ap = Arow + (lane >> 2) * 136 + 2 * (lane & 3);
#pragma unroll 1
    for (int ks = 0; ks < 16; ks++) {
        uint2 b = bf; bf = Bw[(ks + 1) * 128];
        uint2 v0 = *(const uint2*)(ap + ks * 8);
        uint2 v1 = *(const uint2*)(ap + 8 * 136 + ks * 8);
        mma16816(a4, v0.x, v1.x, v0.y, v1.y, b.x, b.y);
    }
}

// epilogue for G1/G2: h = tanh(D + bias) -> f16x2, fragment-permuted position
__device__ __forceinline__ void epi_h(float (&acc)[8][4],
                                      const float* __restrict__ biasg,
                                      u32* __restrict__ hB,
                                      int lane, int mprow, int nq)
{
#pragma unroll
    for (int j = 0; j < 8; j++) {
        int c2 = nq * 32 + j * 4 + (lane & 3);
        float2 bb = *(const float2*)(biasg + 2 * c2);
        u32* p = hB + (mprow + (lane >> 2)) * 136 + posperm(c2);
        p[0]       = h2pack(tanhf_(acc[j][0] + bb.x), tanhf_(acc[j][1] + bb.y));
        p[8 * 136] = h2pack(tanhf_(acc[j][2] + bb.x), tanhf_(acc[j][3] + bb.y));
    }
}

// ---------------- main flow kernel ----------------
__global__ void __launch_bounds__(1024, 1)
flow_kernel(const float* __restrict__ x,
            const float* __restrict__ sb1, const float* __restrict__ sb2,
            const float* __restrict__ sb3, const float* __restrict__ scale,
            const float* __restrict__ tb1, const float* __restrict__ tb2,
            const float* __restrict__ tb3,
            float* __restrict__ out, long long ld_off)
{
    extern __shared__ char smc[];
    u32*   hB  = (u32*)(smc + O_H);
    u32*   xaB = (u32*)(smc + O_XA);
    float* yE  = (float*)(smc + O_YE);
    float* yO  = (float*)(smc + O_YO);
    float* ldp = (float*)(smc + O_LDP);

    const int tid = threadIdx.x, lane = tid & 31, w = tid >> 5;
    const int strip = w >> 2, nq = w & 3, mprow = strip * 16;
    const long long gb = (long long)blockIdx.x * 128;

    {   // init: y split storage + compacted xa (layer 0 active = even cols)
        int r = tid >> 3, q = tid & 7;
        const float4* xr = (const float4*)(x + (gb + r) * 64) + q * 2;
#pragma unroll
        for (int i = 0; i < 2; i++) {
            float4 v = xr[i];
            int j = q * 4 + 2 * i;
            yE[r * 34 + j]     = v.x; yO[r * 34 + j]     = v.y;
            yE[r * 34 + j + 1] = v.z; yO[r * 34 + j + 1] = v.w;
            xaB[r * 24 + posperm(q * 2 + i)] = h2pack(v.x, v.z);
        }
    }
    __syncthreads();

    float ldacc[2] = {0.f, 0.f};
    float acc[8][4];
    float sreg[4];

#pragma unroll 1
    for (int layer = 0; layer < 8; layer++) {
        int op = (layer & 1) ^ 1;
#pragma unroll 1
        for (int net = 0; net < 2; net++) {
            const uint4* Wb = g_wb + (size_t)(layer * 2 + net) * LN4Q;
            const float* b1g = (net ? tb1 : sb1) + layer * 256;
            const float* b2g = (net ? tb2 : sb2) + layer * 256;
            const float* b3g = (net ? tb3 : sb3) + layer * 64;

            BARS();
            gemm8<2, 24>(acc, Wb + nq * 128 + lane, xaB + mprow * 24, lane);
            epi_h(acc, b1g, hB, lane, mprow, nq);
            BARS();
            gemm8<16, 136>(acc, Wb + 1024 + nq * 128 + lane, hB + mprow * 136, lane);
            BARS();
            epi_h(acc, b2g, hB, lane, mprow, nq);
            BARS();
            gemm1(acc[0], (const uint2*)(Wb + 9216) + ((nq >> 1) * 32 + lane) * 2 + (nq & 1),
                  hB + mprow * 136, lane);

            int a = nq * 8 + (lane & 3) * 2;
            int c0 = 2 * a + op;
            float b30 = b3g[c0], b31 = b3g[c0 + 2];
            if (net == 0) {     // s-net: xm=0 at active-out dims -> s = tanh(D+b3)*sc
                const float* scg = scale + layer * 64;
                float sc0 = scg[c0], sc1 = scg[c0 + 2];
#pragma unroll
                for (int rr = 0; rr < 2; rr++) {
                    float s0 = tanhf_(acc[0][rr * 2]     + b30) * sc0;
                    float s1 = tanhf_(acc[0][rr * 2 + 1] + b31) * sc1;
                    sreg[rr * 2]     = s0;
                    sreg[rr * 2 + 1] = s1;
                    ldacc[rr] += s0 + s1;
                }
            } else {            // t-net: y2 = y*exp(s) + (D+b3); write y + next layer's xa
                float* yP = op ? yO : yE;
                int pos = posperm(nq * 4 + (lane & 3));
#pragma unroll
                for (int rr = 0; rr < 2; rr++) {
                    int r = mprow + (lane >> 2) + rr * 8;
                    float2 yv = *(float2*)(yP + r * 34 + a);
                    float y0 = yv.x * __expf(sreg[rr * 2])     + acc[0][rr * 2]     + b30;
                    float y1 = yv.y * __expf(sreg[rr * 2 + 1]) + acc[0][rr * 2 + 1] + b31;
                    *(float2*)(yP + r * 34 + a) = make_float2(y0, y1);
                    xaB[r * 24 + pos] = h2pack(y0, y1);
                }
            }
        }
    }

    // logdet: reduce over the 8 cols of this warp's quarter, then over nq via SMEM
#pragma unroll
    for (int k = 0; k < 2; k++) {
        ldacc[k] += __shfl_xor_sync(0xffffffffu, ldacc[k], 1);
        ldacc[k] += __shfl_xor_sync(0xffffffffu, ldacc[k], 2);
    }
    if ((lane & 3) == 0) {
#pragma unroll
        for (int k = 0; k < 2; k++) {
            int r = mprow + (lane >> 2) + k * 8;
            ldp[r * 4 + nq] = ldacc[k];
        }
    }
    __syncthreads();
    {
        int r = tid >> 3, q = tid & 7;
        float4* orow = (float4*)(out + (gb + r) * 64) + q * 2;
#pragma unroll
        for (int i = 0; i < 2; i++) {
            int j = q * 4 + 2 * i;
            orow[i] = make_float4(yE[r * 34 + j], yO[r * 34 + j],
                                  yE[r * 34 + j + 1], yO[r * 34 + j + 1]);
        }
        if (tid < 128)
            out[ld_off + gb + tid] = ldp[tid * 4] + ldp[tid * 4 + 1]
                                   + ldp[tid * 4 + 2] + ldp[tid * 4 + 3];
    }
}

// ---------------- launch ----------------
extern "C" void kernel_launch(void* const* d_in, const int* in_sizes, int n_in,
                              void* d_out, int out_size)
{
    const float* x     = (const float*)d_in[0];
    const float* sW1   = (const float*)d_in[2];
    const float* sb1   = (const float*)d_in[3];
    const float* sW2   = (const float*)d_in[4];
    const float* sb2   = (const float*)d_in[5];
    const float* sW3   = (const float*)d_in[6];
    const float* sb3   = (const float*)d_in[7];
    const float* scale = (const float*)d_in[8];
    const float* tW1   = (const float*)d_in[9];
    const float* tb1   = (const float*)d_in[10];
    const float* tW2   = (const float*)d_in[11];
    const float* tb2   = (const float*)d_in[12];
    const float* tW3   = (const float*)d_in[13];
    const float* tb3   = (const float*)d_in[14];

    const int B = in_sizes[0] / 64;
    const long long ld_off = (long long)out_size - B;

    cudaFuncSetAttribute(flow_kernel, cudaFuncAttributeMaxDynamicSharedMemorySize,
                         SMEM_REQ);

    prep<<<640, 256>>>(sW1, sW2, sW3, tW1, tW2, tW3);
    flow_kernel<<<B / 128, 1024, SMEM_REQ>>>(x, sb1, sb2, sb3, scale,
                                             tb1, tb2, tb3, (float*)d_out, ld_off);
}

// round 13
// speedup vs baseline: 1.1716x; 1.1716x over previous
#include <cuda_runtime.h>
#include <cuda_fp16.h>
#include <cstdint>

typedef unsigned int u32;

// ---- SMEM layout (byte offsets) ----
#define O_H    0         // u32 h[128][136]  f16x2 pairs, fragment-permuted, stride 136
#define O_XA   69632     // u32 xa[128][24]  compacted active-col activations
#define O_YE   81920     // float yE[128][34]
#define O_YO   99328     // float yO[128][34]
#define O_LDP  116736    // float ldp[128][4]
#define SMEM_REQ 118784

#define LN2 20480        // uint2 per (layer,net) weight block
__device__ __align__(256) uint2 g_wb[16 * LN2 + 2048];   // +16KB pad for prefetch overrun

// ---------------- helpers ----------------
__device__ __forceinline__ float tanhf_(float x) {       // exact-ish (s-path only)
    float e = __expf(2.0f * x);
    return 1.0f - __fdividef(2.0f, e + 1.0f);
}
__device__ __forceinline__ float tanha(float x) {        // MUFU.TANH (h-path)
    float r;
    asm("tanh.approx.f32 %0, %1;" : "=f"(r) : "f"(x));
    return r;
}
__device__ __forceinline__ u32 h2pack(float a, float b) {
    __half2 h = __floats2half2_rn(a, b);
    return *(u32*)&h;
}
// fragment-permuted pair position: pair index pi -> u32 index within row
__device__ __host__ __forceinline__ int posperm(int pi) {
    return ((pi >> 3) << 3) + 2 * (pi & 3) + ((pi >> 2) & 1);
}
__device__ __forceinline__ void mma16816(float* d, u32 a0, u32 a1, u32 a2, u32 a3,
                                         u32 b0, u32 b1) {
    asm volatile(
        "mma.sync.aligned.m16n8k16.row.col.f32.f16.f16.f32 "
        "{%0,%1,%2,%3}, {%4,%5,%6,%7}, {%8,%9}, {%0,%1,%2,%3};"
        : "+f"(d[0]), "+f"(d[1]), "+f"(d[2]), "+f"(d[3])
        : "r"(a0), "r"(a1), "r"(a2), "r"(a3), "r"(b0), "r"(b1));
}
#define BARS() asm volatile("bar.sync %0, %1;" :: "r"(strip + 1), "r"(128) : "memory")

// ---------------- prep: pack fp16 weights into per-lane B-fragment layout ----------------
// Per (layer,net) block of LN2 uint2: G1 @0 (K=32 compacted, 2ks x 32nt x 32lane),
// G2 @2048 (16ks x 32nt x 32, identity folded: W2' = W2 + I),
// G3 @18432 (N=32 compacted, 16ks x 4nt x 32).  Frag uint2 = {f16x2(w0,w1), f16x2(w8,w9)}.
__global__ void prep(const float* __restrict__ sW1, const float* __restrict__ sW2,
                     const float* __restrict__ sW3, const float* __restrict__ tW1,
                     const float* __restrict__ tW2, const float* __restrict__ tW3)
{
    int t = blockIdx.x * blockDim.x + threadIdx.x;
    if (t >= 16 * LN2) return;
    int ln = t / LN2, rem = t % LN2;
    int layer = ln >> 1, net = ln & 1;
    float w0, w1, w8, w9;
    if (rem < 2048) {                       // G1: A cols compacted to mask-active dims
        int ks = rem >> 10, nt = (rem >> 5) & 31, lane = rem & 31;
        int par = layer & 1;
        const float* wr = (net ? tW1 : sW1) + (size_t)layer * 16384
                        + (nt * 8 + (lane >> 2)) * 64 + (ks * 16 + (lane & 3) * 2) * 2 + par;
        w0 = wr[0]; w1 = wr[2]; w8 = wr[16]; w9 = wr[18];
    } else if (rem < 18432) {               // G2 dense, + identity (residual fold)
        int q = rem - 2048;
        int ks = q >> 10, nt = (q >> 5) & 31, lane = q & 31;
        int n = nt * 8 + (lane >> 2);
        int k = ks * 16 + (lane & 3) * 2;
        const float* wr = (net ? tW2 : sW2) + (size_t)layer * 65536 + (size_t)n * 256 + k;
        w0 = wr[0] + (n == k     ? 1.f : 0.f);
        w1 = wr[1] + (n == k + 1 ? 1.f : 0.f);
        w8 = wr[8] + (n == k + 8 ? 1.f : 0.f);
        w9 = wr[9] + (n == k + 9 ? 1.f : 0.f);
    } else {                                // G3: only rows for (1-m)=1 output dims
        int q = rem - 18432;
        int ks = q >> 7, nt = (q >> 5) & 3, lane = q & 31;
        int op = (layer & 1) ^ 1;
        const float* wr = (net ? tW3 : sW3) + (size_t)layer * 16384
                        + (2 * (nt * 8 + (lane >> 2)) + op) * 256 + ks * 16 + (lane & 3) * 2;
        w0 = wr[0]; w1 = wr[1]; w8 = wr[8]; w9 = wr[9];
    }
    g_wb[t] = make_uint2(h2pack(w0, w1), h2pack(w8, w9));
}

// ---------------- GEMM, M=32/warp, 8 n-tiles, B streamed JIT (R6/R8 schedule) ----------------
template<int KS, int AST>
__device__ __forceinline__ void gemm8(float (&acc)[2][8][4],
                                      const uint2* __restrict__ Bw,
                                      const u32* __restrict__ Arow, int lane)
{
#pragma unroll
    for (int mt = 0; mt < 2; mt++)
#pragma unroll
        for (int j = 0; j < 8; j++)
#pragma unroll
            for (int i = 0; i < 4; i++) acc[mt][j][i] = 0.f;

    uint2 bf[4];
#pragma unroll
    for (int j4 = 0; j4 < 4; j4++) bf[j4] = Bw[j4 * 32];
    const u32* ap = Arow + (lane >> 2) * AST + 2 * (lane & 3);

#pragma unroll 1
    for (int ks = 0; ks < KS; ks++) {
        u32 A[2][4];
#pragma unroll
        for (int mt = 0; mt < 2; mt++) {
            const u32* p = ap + mt * (16 * AST) + ks * 8;
            uint2 v0 = *(const uint2*)p;              // a0, a2
            uint2 v1 = *(const uint2*)(p + 8 * AST);  // a1, a3
            A[mt][0] = v0.x; A[mt][2] = v0.y; A[mt][1] = v1.x; A[mt][3] = v1.y;
        }
        const uint2* bq = Bw + ks * 1024;
#pragma unroll
        for (int j4 = 0; j4 < 4; j4++) {
            uint2 b = bf[j4]; bf[j4] = bq[(4 + j4) * 32];
            mma16816(acc[0][j4], A[0][0], A[0][1], A[0][2], A[0][3], b.x, b.y);
            mma16816(acc[1][j4], A[1][0], A[1][1], A[1][2], A[1][3], b.x, b.y);
        }
#pragma unroll
        for (int j4 = 0; j4 < 4; j4++) {
            uint2 b = bf[j4]; bf[j4] = bq[1024 + j4 * 32];
            mma16816(acc[0][4 + j4], A[0][0], A[0][1], A[0][2], A[0][3], b.x, b.y);
            mma16816(acc[1][4 + j4], A[1][0], A[1][1], A[1][2], A[1][3], b.x, b.y);
        }
    }
}

// G3: 1 n-tile/warp (N=32 compacted), K=256, M=32
__device__ __forceinline__ void gemm1(float (&acc)[2][8][4],
                                      const uint2* __restrict__ Bw,
                                      const u32* __restrict__ Arow, int lane)
{
#pragma unroll
    for (int mt = 0; mt < 2; mt++)
#pragma unroll
        for (int i = 0; i < 4; i++) acc[mt][0][i] = 0.f;
    uint2 bf = Bw[0];
    const u32* ap = Arow + (lane >> 2) * 136 + 2 * (lane & 3);
#pragma unroll 1
    for (int ks = 0; ks < 16; ks++) {
        uint2 b = bf; bf = Bw[(ks + 1) * 128];
#pragma unroll
        for (int mt = 0; mt < 2; mt++) {
            const u32* p = ap + mt * (16 * 136) + ks * 8;
            uint2 v0 = *(const uint2*)p;
            uint2 v1 = *(const uint2*)(p + 8 * 136);
            mma16816(acc[mt][0], v0.x, v1.x, v0.y, v1.y, b.x, b.y);
        }
    }
}

// epilogue for G1/G2: h = tanh.approx(D + bias) -> f16x2, fragment-permuted position
__device__ __forceinline__ void epi_h(float (&acc)[2][8][4],
                                      const float* __restrict__ biasg,
                                      u32* __restrict__ hB,
                                      int lane, int mprow, int nq)
{
#pragma unroll
    for (int j = 0; j < 8; j++) {
        int c2 = nq * 32 + j * 4 + (lane & 3);
        float2 bb = *(const float2*)(biasg + 2 * c2);
        int pos = posperm(c2);
#pragma unroll
        for (int mt = 0; mt < 2; mt++) {
            u32* p = hB + (mprow + mt * 16 + (lane >> 2)) * 136 + pos;
            p[0]       = h2pack(tanha(acc[mt][j][0] + bb.x), tanha(acc[mt][j][1] + bb.y));
            p[8 * 136] = h2pack(tanha(acc[mt][j][2] + bb.x), tanha(acc[mt][j][3] + bb.y));
        }
    }
}

// ---------------- main flow kernel ----------------
__global__ void __launch_bounds__(512, 1)
flow_kernel(const float* __restrict__ x,
            const float* __restrict__ sb1, const float* __restrict__ sb2,
            const float* __restrict__ sb3, const float* __restrict__ scale,
            const float* __restrict__ tb1, const float* __restrict__ tb2,
            const float* __restrict__ tb3,
            float* __restrict__ out, long long ld_off)
{
    extern __shared__ char smc[];
    u32*   hB  = (u32*)(smc + O_H);
    u32*   xaB = (u32*)(smc + O_XA);
    float* yE  = (float*)(smc + O_YE);
    float* yO  = (float*)(smc + O_YO);
    float* ldp = (float*)(smc + O_LDP);

    const int tid = threadIdx.x, lane = tid & 31, w = tid >> 5;
    const int strip = w >> 2, nq = w & 3, mprow = strip * 32;
    const long long gb = (long long)blockIdx.x * 128;

    {   // init: y split storage + compacted xa (layer 0 active = even cols)
        int r = tid >> 2, q = tid & 3;
        const float4* xr = (const float4*)(x + (gb + r) * 64) + q * 4;
#pragma unroll
        for (int i = 0; i < 4; i++) {
            float4 v = xr[i];
            int j = q * 8 + 2 * i;
            yE[r * 34 + j]     = v.x; yO[r * 34 + j]     = v.y;
            yE[r * 34 + j + 1] = v.z; yO[r * 34 + j + 1] = v.w;
            xaB[r * 24 + posperm(q * 4 + i)] = h2pack(v.x, v.z);
        }
    }
    __syncthreads();

    float ldacc[4] = {0.f, 0.f, 0.f, 0.f};   // per (mt, rr)
    float acc[2][8][4];
    float sreg[8];

#pragma unroll 1
    for (int layer = 0; layer < 8; layer++) {
        int op = (layer & 1) ^ 1;
#pragma unroll 1
        for (int net = 0; net < 2; net++) {
            const uint2* Wb = g_wb + (size_t)(layer * 2 + net) * LN2;
            const float* b1g = (net ? tb1 : sb1) + layer * 256;
            const float* b2g = (net ? tb2 : sb2) + layer * 256;
            const float* b3g = (net ? tb3 : sb3) + layer * 64;

            BARS();
            gemm8<2, 24>(acc, Wb + nq * 256 + lane, xaB + mprow * 24, lane);
            epi_h(acc, b1g, hB, lane, mprow, nq);
            BARS();
            gemm8<16, 136>(acc, Wb + 2048 + nq * 256 + lane, hB + mprow * 136, lane);
            BARS();
            epi_h(acc, b2g, hB, lane, mprow, nq);
            BARS();
            gemm1(acc, Wb + 18432 + nq * 32 + lane, hB + mprow * 136, lane);

            int a = nq * 8 + (lane & 3) * 2;
            int c0 = 2 * a + op;
            float b30 = b3g[c0], b31 = b3g[c0 + 2];
            if (net == 0) {     // s-net: xm=0 at active-out dims -> s = tanh(D+b3)*sc (exact)
                const float* scg = scale + layer * 64;
                float sc0 = scg[c0], sc1 = scg[c0 + 2];
#pragma unroll
                for (int mt = 0; mt < 2; mt++)
#pragma unroll
                    for (int rr = 0; rr < 2; rr++) {
                        float s0 = tanhf_(acc[mt][0][rr * 2]     + b30) * sc0;
                        float s1 = tanhf_(acc[mt][0][rr * 2 + 1] + b31) * sc1;
                        sreg[mt * 4 + rr * 2]     = s0;
                        sreg[mt * 4 + rr * 2 + 1] = s1;
                        ldacc[mt * 2 + rr] += s0 + s1;
                    }
            } else {            // t-net: y2 = y*exp(s) + (D+b3); write y + next layer's xa
                float* yP = op ? yO : yE;
                int pos = posperm(nq * 4 + (lane & 3));
#pragma unroll
                for (int mt = 0; mt < 2; mt++)
#pragma unroll
                    for (int rr = 0; rr < 2; rr++) {
                        int r = mprow + mt * 16 + (lane >> 2) + rr * 8;
                        float2 yv = *(float2*)(yP + r * 34 + a);
                        float y0 = yv.x * __expf(sreg[mt * 4 + rr * 2])
                                 + acc[mt][0][rr * 2] + b30;
                        float y1 = yv.y * __expf(sreg[mt * 4 + rr * 2 + 1])
                                 + acc[mt][0][rr * 2 + 1] + b31;
                        *(float2*)(yP + r * 34 + a) = make_float2(y0, y1);
                        xaB[r * 24 + pos] = h2pack(y0, y1);
                    }
            }
        }
    }

#pragma unroll
    for (int k = 0; k < 4; k++) {
        ldacc[k] += __shfl_xor_sync(0xffffffffu, ldacc[k], 1);
        ldacc[k] += __shfl_xor_sync(0xffffffffu, ldacc[k], 2);
    }
    if ((lane & 3) == 0) {
#pragma unroll
        for (int k = 0; k < 4; k++) {
            int r = mprow + (k >> 1) * 16 + (lane >> 2) + (k & 1) * 8;
            ldp[r * 4 + nq] = ldacc[k];
        }
    }
    __syncthreads();
    {
        int r = tid >> 2, q = tid & 3;
        float4* orow = (float4*)(out + (gb + r) * 64) + q * 4;
#pragma unroll
        for (int i = 0; i < 4; i++) {
            int j = q * 8 + 2 * i;
            orow[i] = make_float4(yE[r * 34 + j], yO[r * 34 + j],
                                  yE[r * 34 + j + 1], yO[r * 34 + j + 1]);
        }
        if (tid < 128)
            out[ld_off + gb + tid] = ldp[tid * 4] + ldp[tid * 4 + 1]
                                   + ldp[tid * 4 + 2] + ldp[tid * 4 + 3];
    }
}

// ---------------- launch ----------------
extern "C" void kernel_launch(void* const* d_in, const int* in_sizes, int n_in,
                              void* d_out, int out_size)
{
    const float* x     = (const float*)d_in[0];
    const float* sW1   = (const float*)d_in[2];
    const float* sb1   = (const float*)d_in[3];
    const float* sW2   = (const float*)d_in[4];
    const float* sb2   = (const float*)d_in[5];
    const float* sW3   = (const float*)d_in[6];
    const float* sb3   = (const float*)d_in[7];
    const float* scale = (const float*)d_in[8];
    const float* tW1   = (const float*)d_in[9];
    const float* tb1   = (const float*)d_in[10];
    const float* tW2   = (const float*)d_in[11];
    const float* tb2   = (const float*)d_in[12];
    const float* tW3   = (const float*)d_in[13];
    const float* tb3   = (const float*)d_in[14];

    const int B = in_sizes[0] / 64;
    const long long ld_off = (long long)out_size - B;

    cudaFuncSetAttribute(flow_kernel, cudaFuncAttributeMaxDynamicSharedMemorySize,
                         SMEM_REQ);

    prep<<<1280, 256>>>(sW1, sW2, sW3, tW1, tW2, tW3);
    flow_kernel<<<B / 128, 512, SMEM_REQ>>>(x, sb1, sb2, sb3, scale,
                                            tb1, tb2, tb3, (float*)d_out, ld_off);
}